// round 1
// baseline (speedup 1.0000x reference)
#include <cuda_runtime.h>
#include <math.h>

#define ROWS   32768
#define DDIM   1024
#define MDIM   512
#define BATCH  4
#define SEQ    8192
#define CHUNK  128
#define NCHUNK 64   // SEQ / CHUNK

// ---------------- scratch (static device globals; no allocations) -----------
__device__ __align__(128) float g_h   [ROWS * MDIM];
__device__ __align__(128) float g_q   [ROWS * MDIM];
__device__ __align__(128) float g_k   [ROWS * MDIM];
__device__ __align__(128) float g_v   [ROWS * MDIM];
__device__ __align__(128) float g_p   [ROWS * MDIM];   // P = gelu(k@W1); reused for "retrieved"
__device__ __align__(128) float g_u   [ROWS * MDIM];
__device__ __align__(128) float g_mem [ROWS * MDIM];
__device__ __align__(128) float g_carry[BATCH * NCHUNK * MDIM];
__device__ __align__(128) float g_pref [BATCH * NCHUNK * MDIM];

__device__ __forceinline__ float gelu_tanh(float x) {
    float x3 = x * x * x;
    float t  = tanhf(0.7978845608028654f * (x + 0.044715f * x3));
    return 0.5f * x * (1.0f + t);
}

// ---------------- generic 128x128x16 fp32 tiled GEMM ------------------------
// A [Mrows,K] row-major, B [K,N] row-major, C [Mrows,N].
// MODE 0: C = A@B + bias[col]
// MODE 1: C = gelu(A@B)
// MODE 2: C = (*scal) * (extra - A@B)            (u = lr*(v - pred))
// MODE 3: C = A@B + bias[col] + extra            (residual out-projection)
template <int MODE>
__global__ __launch_bounds__(256) void gemm_kernel(
    const float* __restrict__ A, const float* __restrict__ Bm,
    const float* __restrict__ bias, const float* __restrict__ extra,
    const float* __restrict__ scal, float* __restrict__ C,
    int K, int N)
{
    __shared__ float sA[16][128 + 4];
    __shared__ float sB[16][128 + 4];

    const int bx = blockIdx.x, by = blockIdx.y;
    const int t  = threadIdx.x;
    const int tx = t & 15, ty = t >> 4;

    const float* Ab = A + (size_t)by * 128 * K;
    const float* Bb = Bm + (size_t)bx * 128;

    float acc[8][8];
#pragma unroll
    for (int i = 0; i < 8; i++)
#pragma unroll
        for (int j = 0; j < 8; j++) acc[i][j] = 0.0f;

    for (int k0 = 0; k0 < K; k0 += 16) {
        // load A tile 128x16 (store transposed into sA[k][m])
#pragma unroll
        for (int i = 0; i < 2; i++) {
            int idx = t * 2 + i;          // 0..511
            int row = idx >> 2;           // 0..127
            int kc4 = idx & 3;            // 0..3
            float4 va = *reinterpret_cast<const float4*>(
                Ab + (size_t)row * K + k0 + kc4 * 4);
            sA[kc4 * 4 + 0][row] = va.x;
            sA[kc4 * 4 + 1][row] = va.y;
            sA[kc4 * 4 + 2][row] = va.z;
            sA[kc4 * 4 + 3][row] = va.w;
        }
        // load B tile 16x128
#pragma unroll
        for (int i = 0; i < 2; i++) {
            int idx = t * 2 + i;          // 0..511
            int row = idx >> 5;           // 0..15
            int c4  = idx & 31;           // 0..31
            float4 vb = *reinterpret_cast<const float4*>(
                Bb + (size_t)(k0 + row) * N + c4 * 4);
            *reinterpret_cast<float4*>(&sB[row][c4 * 4]) = vb;
        }
        __syncthreads();

#pragma unroll
        for (int kk = 0; kk < 16; kk++) {
            float a[8], b[8];
#pragma unroll
            for (int i = 0; i < 8; i++) a[i] = sA[kk][ty * 8 + i];
#pragma unroll
            for (int j = 0; j < 8; j++) b[j] = sB[kk][tx * 8 + j];
#pragma unroll
            for (int i = 0; i < 8; i++)
#pragma unroll
                for (int j = 0; j < 8; j++)
                    acc[i][j] = fmaf(a[i], b[j], acc[i][j]);
        }
        __syncthreads();
    }

    const float lr = (MODE == 2) ? *scal : 0.0f;
#pragma unroll
    for (int i = 0; i < 8; i++) {
        size_t r   = (size_t)by * 128 + ty * 8 + i;
        size_t off = r * N + (size_t)bx * 128 + tx * 8;
#pragma unroll
        for (int j = 0; j < 8; j++) {
            int    c    = bx * 128 + tx * 8 + j;
            float  vacc = acc[i][j];
            float  outv;
            if (MODE == 0)      outv = vacc + bias[c];
            else if (MODE == 1) outv = gelu_tanh(vacc);
            else if (MODE == 2) outv = lr * (extra[off + j] - vacc);
            else                outv = vacc + bias[c] + extra[off + j];
            C[off + j] = outv;
        }
    }
}

// ---------------- LayerNorm: one warp per row of 512 ------------------------
__global__ __launch_bounds__(256) void ln_kernel(
    float* __restrict__ Z, const float* __restrict__ g, const float* __restrict__ b)
{
    int warp = threadIdx.x >> 5;
    int lane = threadIdx.x & 31;
    size_t row = (size_t)blockIdx.x * 8 + warp;
    float* zr = Z + row * MDIM;

    float4 v[4];
    float s = 0.0f, s2 = 0.0f;
#pragma unroll
    for (int i = 0; i < 4; i++) {
        v[i] = *reinterpret_cast<const float4*>(zr + (lane + 32 * i) * 4);
        s  += v[i].x + v[i].y + v[i].z + v[i].w;
        s2 += v[i].x * v[i].x + v[i].y * v[i].y + v[i].z * v[i].z + v[i].w * v[i].w;
    }
#pragma unroll
    for (int o = 16; o; o >>= 1) {
        s  += __shfl_xor_sync(0xffffffffu, s,  o);
        s2 += __shfl_xor_sync(0xffffffffu, s2, o);
    }
    float mu   = s  * (1.0f / MDIM);
    float var  = s2 * (1.0f / MDIM) - mu * mu;
    float rstd = rsqrtf(var + 1e-5f);
#pragma unroll
    for (int i = 0; i < 4; i++) {
        int cbase = (lane + 32 * i) * 4;
        float4 gv = *reinterpret_cast<const float4*>(g + cbase);
        float4 bv = *reinterpret_cast<const float4*>(b + cbase);
        float4 o;
        o.x = (v[i].x - mu) * rstd * gv.x + bv.x;
        o.y = (v[i].y - mu) * rstd * gv.y + bv.y;
        o.z = (v[i].z - mu) * rstd * gv.z + bv.z;
        o.w = (v[i].w - mu) * rstd * gv.w + bv.w;
        *reinterpret_cast<float4*>(zr + cbase) = o;
    }
}

// ---------------- 3-phase gated scan (constant gate g) ----------------------
// mem[s] = g*mem[s-1] + u[s]  along S, per (b, m)
__global__ __launch_bounds__(512) void scan1(
    const float* __restrict__ u, float* __restrict__ loc,
    float* __restrict__ carry, const float* __restrict__ ffp)
{
    int m = threadIdx.x;   // 0..511
    int c = blockIdx.x;    // chunk 0..63
    int b = blockIdx.y;    // batch 0..3
    float g = 1.0f / (1.0f + expf(-*ffp));
    size_t base = ((size_t)b * SEQ + (size_t)c * CHUNK) * MDIM + m;
    float acc = 0.0f;
    for (int s = 0; s < CHUNK; s++) {
        size_t idx = base + (size_t)s * MDIM;
        acc = fmaf(g, acc, u[idx]);
        loc[idx] = acc;
    }
    carry[((size_t)b * NCHUNK + c) * MDIM + m] = acc;
}

__global__ __launch_bounds__(512) void scan2(
    const float* __restrict__ carry, float* __restrict__ pref,
    const float* __restrict__ ffp)
{
    int m = threadIdx.x;
    int b = blockIdx.x;
    float g  = 1.0f / (1.0f + expf(-*ffp));
    float gL = powf(g, (float)CHUNK);
    float P = 0.0f;
    for (int c = 0; c < NCHUNK; c++) {
        size_t idx = ((size_t)b * NCHUNK + c) * MDIM + m;
        pref[idx] = P;                 // exclusive: mem at end of previous chunk
        P = fmaf(gL, P, carry[idx]);
    }
}

__global__ __launch_bounds__(512) void scan3(
    const float* __restrict__ loc, const float* __restrict__ pref,
    const float* __restrict__ q, float* __restrict__ ret,
    const float* __restrict__ ffp)
{
    int m = threadIdx.x;
    int c = blockIdx.x;
    int b = blockIdx.y;
    float g = 1.0f / (1.0f + expf(-*ffp));
    float P = pref[((size_t)b * NCHUNK + c) * MDIM + m];
    size_t base = ((size_t)b * SEQ + (size_t)c * CHUNK) * MDIM + m;
    float w = g;
    for (int s = 0; s < CHUNK; s++) {
        size_t idx = base + (size_t)s * MDIM;
        float mem = fmaf(w, P, loc[idx]);
        ret[idx] = q[idx] * mem;
        w *= g;
    }
}

// ---------------- launch ----------------------------------------------------
extern "C" void kernel_launch(void* const* d_in, const int* in_sizes, int n_in,
                              void* d_out, int out_size)
{
    const float* x    = (const float*)d_in[0];
    const float* Wd   = (const float*)d_in[1];
    const float* bd   = (const float*)d_in[2];
    const float* Wq   = (const float*)d_in[3];
    const float* bq   = (const float*)d_in[4];
    const float* Wk   = (const float*)d_in[5];
    const float* bk   = (const float*)d_in[6];
    const float* Wv   = (const float*)d_in[7];
    const float* bv   = (const float*)d_in[8];
    const float* gq   = (const float*)d_in[9];
    const float* bqln = (const float*)d_in[10];
    const float* gk   = (const float*)d_in[11];
    const float* bkln = (const float*)d_in[12];
    const float* W1   = (const float*)d_in[13];
    const float* W2   = (const float*)d_in[14];
    const float* Wu   = (const float*)d_in[15];
    const float* bu   = (const float*)d_in[16];
    const float* lr   = (const float*)d_in[17];
    const float* ff   = (const float*)d_in[18];
    float* out = (float*)d_out;

    float *h, *q, *k, *v, *p, *u, *memb, *carry, *pref;
    cudaGetSymbolAddress((void**)&h,     g_h);
    cudaGetSymbolAddress((void**)&q,     g_q);
    cudaGetSymbolAddress((void**)&k,     g_k);
    cudaGetSymbolAddress((void**)&v,     g_v);
    cudaGetSymbolAddress((void**)&p,     g_p);
    cudaGetSymbolAddress((void**)&u,     g_u);
    cudaGetSymbolAddress((void**)&memb,  g_mem);
    cudaGetSymbolAddress((void**)&carry, g_carry);
    cudaGetSymbolAddress((void**)&pref,  g_pref);

    dim3 tb(256);
    dim3 gM(MDIM / 128, ROWS / 128);   // N=512 outputs
    dim3 gD(DDIM / 128, ROWS / 128);   // N=1024 outputs

    // h = x @ Wd + bd
    gemm_kernel<0><<<gM, tb>>>(x, Wd, bd, nullptr, nullptr, h, DDIM, MDIM);
    // q̂ / k̂ / v
    gemm_kernel<0><<<gM, tb>>>(h, Wq, bq, nullptr, nullptr, q, MDIM, MDIM);
    gemm_kernel<0><<<gM, tb>>>(h, Wk, bk, nullptr, nullptr, k, MDIM, MDIM);
    gemm_kernel<0><<<gM, tb>>>(h, Wv, bv, nullptr, nullptr, v, MDIM, MDIM);
    // LayerNorms (in place)
    ln_kernel<<<ROWS / 8, 256>>>(q, gq, bqln);
    ln_kernel<<<ROWS / 8, 256>>>(k, gk, bkln);
    // P = gelu(k @ W1)
    gemm_kernel<1><<<gM, tb>>>(k, W1, nullptr, nullptr, nullptr, p, MDIM, MDIM);
    // u = lr * (v - P @ W2)
    gemm_kernel<2><<<gM, tb>>>(p, W2, nullptr, v, lr, u, MDIM, MDIM);
    // gated scan -> mem; retrieved = q * mem (into p, reused)
    scan1<<<dim3(NCHUNK, BATCH), MDIM>>>(u, memb, carry, ff);
    scan2<<<BATCH, MDIM>>>(carry, pref, ff);
    scan3<<<dim3(NCHUNK, BATCH), MDIM>>>(memb, pref, q, p, ff);
    // out = x + retrieved @ Wu + bu
    gemm_kernel<3><<<gD, tb>>>(p, Wu, bu, x, nullptr, out, MDIM, DDIM);
}

// round 2
// speedup vs baseline: 4.9362x; 4.9362x over previous
#include <cuda_runtime.h>
#include <cuda_bf16.h>
#include <math.h>

#define ROWS   32768
#define DDIM   1024
#define MDIM   512
#define BATCH  4
#define SEQ    8192
#define CHUNK  128
#define NCHUNK 64

typedef __nv_bfloat16 bf16;

// ---------------- scratch (static device globals; no allocations) -----------
// bf16 activations
__device__ __align__(128) bf16  g_xb [ROWS * DDIM];
__device__ __align__(128) bf16  g_hb [ROWS * MDIM];
__device__ __align__(128) bf16  g_qb [ROWS * MDIM];
__device__ __align__(128) bf16  g_kb [ROWS * MDIM];
__device__ __align__(128) bf16  g_pb [ROWS * MDIM];
__device__ __align__(128) bf16  g_rb [ROWS * MDIM];
// fp32 intermediates
__device__ __align__(128) float g_qf [ROWS * MDIM];   // pre-LN q-hat
__device__ __align__(128) float g_kf [ROWS * MDIM];   // pre-LN k-hat
__device__ __align__(128) float g_v  [ROWS * MDIM];
__device__ __align__(128) float g_u  [ROWS * MDIM];
__device__ __align__(128) float g_loc[ROWS * MDIM];
__device__ __align__(128) float g_carry[BATCH * NCHUNK * MDIM];
__device__ __align__(128) float g_pref [BATCH * NCHUNK * MDIM];
// bf16 weights
__device__ __align__(128) bf16  g_Wdb[DDIM * MDIM];
__device__ __align__(128) bf16  g_Wqb[MDIM * MDIM];
__device__ __align__(128) bf16  g_Wkb[MDIM * MDIM];
__device__ __align__(128) bf16  g_Wvb[MDIM * MDIM];
__device__ __align__(128) bf16  g_W1b[MDIM * MDIM];
__device__ __align__(128) bf16  g_W2b[MDIM * MDIM];
__device__ __align__(128) bf16  g_Wub[MDIM * DDIM];

__device__ __forceinline__ float gelu_tanh(float x) {
    float x3 = x * x * x;
    float t  = tanhf(0.7978845608028654f * (x + 0.044715f * x3));
    return 0.5f * x * (1.0f + t);
}

// ---------------- float -> bf16 conversion ----------------------------------
__global__ __launch_bounds__(256) void cvt_kernel(const float* __restrict__ s,
                                                  bf16* __restrict__ d, int n4)
{
    int i = blockIdx.x * 256 + threadIdx.x;
    if (i >= n4) return;
    float4 v = reinterpret_cast<const float4*>(s)[i];
    __nv_bfloat162 a = __floats2bfloat162_rn(v.x, v.y);
    __nv_bfloat162 b = __floats2bfloat162_rn(v.z, v.w);
    uint2 o;
    o.x = *reinterpret_cast<unsigned*>(&a);
    o.y = *reinterpret_cast<unsigned*>(&b);
    reinterpret_cast<uint2*>(d)[i] = o;
}

// ---------------- bf16 tensor-core GEMM (mma.sync m16n8k16) -----------------
// A [Mrows,K] row-major bf16, B [K,N] row-major bf16.
// MODE 0: out = A@B + bias[col]
// MODE 1: out = gelu(A@B)
// MODE 2: out = (*scal) * (extra - A@B)
// MODE 3: out = A@B + bias[col] + extra
// BF16OUT: write bf16 (Cb) else fp32 (Cf)
#define BM 128
#define BN 128
#define BK 32
#define PA 40   // sA row stride (elems)
#define PB 136  // sB row stride (elems)

__device__ __forceinline__ void cp16(unsigned saddr, const void* g) {
    asm volatile("cp.async.cg.shared.global [%0], [%1], 16;\n" :: "r"(saddr), "l"(g));
}
__device__ __forceinline__ void cp_commit() { asm volatile("cp.async.commit_group;\n"); }
template<int N> __device__ __forceinline__ void cp_wait() {
    asm volatile("cp.async.wait_group %0;\n" :: "n"(N));
}

template <int MODE, bool BF16OUT>
__global__ __launch_bounds__(256, 2) void mma_gemm(
    const bf16* __restrict__ A, const bf16* __restrict__ B,
    const float* __restrict__ bias, const float* __restrict__ extra,
    const float* __restrict__ scal,
    float* __restrict__ Cf, bf16* __restrict__ Cb,
    int K, int N)
{
    __shared__ __align__(16) bf16 sA[2][BM][PA];
    __shared__ __align__(16) bf16 sB[2][BK][PB];

    const int t    = threadIdx.x;
    const int lane = t & 31;
    const int w    = t >> 5;
    const int wm   = w & 1;        // 0..1  (64 rows each)
    const int wn   = w >> 1;       // 0..3  (32 cols each)
    const int blockRow = blockIdx.y * BM;
    const int blockCol = blockIdx.x * BN;

    const unsigned sA0 = (unsigned)__cvta_generic_to_shared(&sA[0][0][0]);
    const unsigned sB0 = (unsigned)__cvta_generic_to_shared(&sB[0][0][0]);
    const unsigned stA = (unsigned)(BM * PA * sizeof(bf16));
    const unsigned stB = (unsigned)(BK * PB * sizeof(bf16));

    // cp.async source/dest mapping
    // A: 512 chunks of 16B: chunk c -> row c>>2, kgrp c&3
    const int acr = (t * 2) >> 2;          // rows for this thread's two chunks share? no:
    // compute per-chunk below instead.

    float acc[4][4][4];
#pragma unroll
    for (int mi = 0; mi < 4; mi++)
#pragma unroll
        for (int ni = 0; ni < 4; ni++)
#pragma unroll
            for (int r = 0; r < 4; r++) acc[mi][ni][r] = 0.0f;

    const int KT = K / BK;

    auto load_stage = [&](int st, int k0) {
#pragma unroll
        for (int i = 0; i < 2; i++) {
            int c   = t * 2 + i;           // 0..511
            int row = c >> 2;
            int kg  = c & 3;
            cp16(sA0 + st * stA + (unsigned)((row * PA + kg * 8) * 2),
                 A + (size_t)(blockRow + row) * K + k0 + kg * 8);
        }
#pragma unroll
        for (int i = 0; i < 2; i++) {
            int c   = t * 2 + i;           // 0..511
            int row = c >> 4;              // 0..31
            int ng  = c & 15;              // 0..15
            cp16(sB0 + st * stB + (unsigned)((row * PB + ng * 8) * 2),
                 B + (size_t)(k0 + row) * N + blockCol + ng * 8);
        }
        cp_commit();
    };

    load_stage(0, 0);

    // ldmatrix lane-offsets (element units)
    const int l15 = lane & 15;
    const int l16 = lane >> 4;

    for (int kt = 0; kt < KT; kt++) {
        const int cur = kt & 1;
        if (kt + 1 < KT) load_stage((kt + 1) & 1, (kt + 1) * BK);
        if (kt + 1 < KT) cp_wait<1>(); else cp_wait<0>();
        __syncthreads();

#pragma unroll
        for (int ks = 0; ks < 2; ks++) {
            unsigned afr[4][4];
#pragma unroll
            for (int mi = 0; mi < 4; mi++) {
                unsigned addr = sA0 + cur * stA +
                    (unsigned)(((wm * 64 + mi * 16 + l15) * PA + ks * 16 + l16 * 8) * 2);
                asm volatile("ldmatrix.sync.aligned.m8n8.x4.shared.b16 {%0,%1,%2,%3}, [%4];\n"
                    : "=r"(afr[mi][0]), "=r"(afr[mi][1]), "=r"(afr[mi][2]), "=r"(afr[mi][3])
                    : "r"(addr));
            }
            unsigned bfr[2][4];
#pragma unroll
            for (int n2 = 0; n2 < 2; n2++) {
                unsigned addr = sB0 + cur * stB +
                    (unsigned)(((ks * 16 + l15) * PB + wn * 32 + n2 * 16 + l16 * 8) * 2);
                asm volatile("ldmatrix.sync.aligned.m8n8.x4.trans.shared.b16 {%0,%1,%2,%3}, [%4];\n"
                    : "=r"(bfr[n2][0]), "=r"(bfr[n2][1]), "=r"(bfr[n2][2]), "=r"(bfr[n2][3])
                    : "r"(addr));
            }
#pragma unroll
            for (int mi = 0; mi < 4; mi++)
#pragma unroll
                for (int ni = 0; ni < 4; ni++) {
                    unsigned b0 = bfr[ni >> 1][(ni & 1) * 2 + 0];
                    unsigned b1 = bfr[ni >> 1][(ni & 1) * 2 + 1];
                    asm volatile(
                        "mma.sync.aligned.m16n8k16.row.col.f32.bf16.bf16.f32 "
                        "{%0,%1,%2,%3}, {%4,%5,%6,%7}, {%8,%9}, {%0,%1,%2,%3};\n"
                        : "+f"(acc[mi][ni][0]), "+f"(acc[mi][ni][1]),
                          "+f"(acc[mi][ni][2]), "+f"(acc[mi][ni][3])
                        : "r"(afr[mi][0]), "r"(afr[mi][1]), "r"(afr[mi][2]), "r"(afr[mi][3]),
                          "r"(b0), "r"(b1));
                }
        }
        __syncthreads();
    }

    // epilogue
    const int grp = lane >> 2;
    const int t4  = lane & 3;
    const float lr = (MODE == 2) ? *scal : 0.0f;

#pragma unroll
    for (int mi = 0; mi < 4; mi++) {
#pragma unroll
        for (int ni = 0; ni < 4; ni++) {
            int c = blockCol + wn * 32 + ni * 8 + 2 * t4;
            float b0 = 0.f, b1 = 0.f;
            if (MODE == 0 || MODE == 3) { b0 = bias[c]; b1 = bias[c + 1]; }
#pragma unroll
            for (int h = 0; h < 2; h++) {
                size_t r   = (size_t)(blockRow + wm * 64 + mi * 16 + grp + h * 8);
                size_t off = r * N + c;
                float v0 = acc[mi][ni][h * 2 + 0];
                float v1 = acc[mi][ni][h * 2 + 1];
                float o0, o1;
                if (MODE == 0)      { o0 = v0 + b0; o1 = v1 + b1; }
                else if (MODE == 1) { o0 = gelu_tanh(v0); o1 = gelu_tanh(v1); }
                else if (MODE == 2) { o0 = lr * (extra[off] - v0); o1 = lr * (extra[off + 1] - v1); }
                else                { o0 = v0 + b0 + extra[off]; o1 = v1 + b1 + extra[off + 1]; }
                if (BF16OUT) {
                    __nv_bfloat162 p = __floats2bfloat162_rn(o0, o1);
                    *reinterpret_cast<unsigned*>(Cb + off) = *reinterpret_cast<unsigned*>(&p);
                } else {
                    float2 p = make_float2(o0, o1);
                    *reinterpret_cast<float2*>(Cf + off) = p;
                }
            }
        }
    }
}

// ---------------- LayerNorm: fp32 in, bf16 out, warp per row ----------------
__global__ __launch_bounds__(256) void ln_kernel(
    const float* __restrict__ Z, const float* __restrict__ g,
    const float* __restrict__ b, bf16* __restrict__ out)
{
    int warp = threadIdx.x >> 5;
    int lane = threadIdx.x & 31;
    size_t row = (size_t)blockIdx.x * 8 + warp;
    const float* zr = Z + row * MDIM;

    float4 v[4];
    float s = 0.0f, s2 = 0.0f;
#pragma unroll
    for (int i = 0; i < 4; i++) {
        v[i] = *reinterpret_cast<const float4*>(zr + (lane + 32 * i) * 4);
        s  += v[i].x + v[i].y + v[i].z + v[i].w;
        s2 += v[i].x * v[i].x + v[i].y * v[i].y + v[i].z * v[i].z + v[i].w * v[i].w;
    }
#pragma unroll
    for (int o = 16; o; o >>= 1) {
        s  += __shfl_xor_sync(0xffffffffu, s,  o);
        s2 += __shfl_xor_sync(0xffffffffu, s2, o);
    }
    float mu   = s  * (1.0f / MDIM);
    float var  = s2 * (1.0f / MDIM) - mu * mu;
    float rstd = rsqrtf(var + 1e-5f);
#pragma unroll
    for (int i = 0; i < 4; i++) {
        int cbase = (lane + 32 * i) * 4;
        float4 gv = *reinterpret_cast<const float4*>(g + cbase);
        float4 bv = *reinterpret_cast<const float4*>(b + cbase);
        float o0 = (v[i].x - mu) * rstd * gv.x + bv.x;
        float o1 = (v[i].y - mu) * rstd * gv.y + bv.y;
        float o2 = (v[i].z - mu) * rstd * gv.z + bv.z;
        float o3 = (v[i].w - mu) * rstd * gv.w + bv.w;
        __nv_bfloat162 p0 = __floats2bfloat162_rn(o0, o1);
        __nv_bfloat162 p1 = __floats2bfloat162_rn(o2, o3);
        uint2 pk;
        pk.x = *reinterpret_cast<unsigned*>(&p0);
        pk.y = *reinterpret_cast<unsigned*>(&p1);
        *reinterpret_cast<uint2*>(out + row * MDIM + cbase) = pk;
    }
}

// ---------------- 3-phase gated scan (constant gate g) ----------------------
__global__ __launch_bounds__(512) void scan1(
    const float* __restrict__ u, float* __restrict__ loc,
    float* __restrict__ carry, const float* __restrict__ ffp)
{
    int m = threadIdx.x;
    int c = blockIdx.x;
    int b = blockIdx.y;
    float g = 1.0f / (1.0f + expf(-*ffp));
    size_t base = ((size_t)b * SEQ + (size_t)c * CHUNK) * MDIM + m;
    float acc = 0.0f;
    for (int s = 0; s < CHUNK; s++) {
        size_t idx = base + (size_t)s * MDIM;
        acc = fmaf(g, acc, u[idx]);
        loc[idx] = acc;
    }
    carry[((size_t)b * NCHUNK + c) * MDIM + m] = acc;
}

__global__ __launch_bounds__(512) void scan2(
    const float* __restrict__ carry, float* __restrict__ pref,
    const float* __restrict__ ffp)
{
    int m = threadIdx.x;
    int b = blockIdx.x;
    float g  = 1.0f / (1.0f + expf(-*ffp));
    float gL = powf(g, (float)CHUNK);
    float P = 0.0f;
    for (int c = 0; c < NCHUNK; c++) {
        size_t idx = ((size_t)b * NCHUNK + c) * MDIM + m;
        pref[idx] = P;
        P = fmaf(gL, P, carry[idx]);
    }
}

__global__ __launch_bounds__(512) void scan3(
    const float* __restrict__ loc, const float* __restrict__ pref,
    const bf16* __restrict__ q, bf16* __restrict__ ret,
    const float* __restrict__ ffp)
{
    int m = threadIdx.x;
    int c = blockIdx.x;
    int b = blockIdx.y;
    float g = 1.0f / (1.0f + expf(-*ffp));
    float P = pref[((size_t)b * NCHUNK + c) * MDIM + m];
    size_t base = ((size_t)b * SEQ + (size_t)c * CHUNK) * MDIM + m;
    float w = g;
    for (int s = 0; s < CHUNK; s++) {
        size_t idx = base + (size_t)s * MDIM;
        float mem = fmaf(w, P, loc[idx]);
        ret[idx] = __float2bfloat16(__bfloat162float(q[idx]) * mem);
        w *= g;
    }
}

// ---------------- launch ----------------------------------------------------
extern "C" void kernel_launch(void* const* d_in, const int* in_sizes, int n_in,
                              void* d_out, int out_size)
{
    const float* x    = (const float*)d_in[0];
    const float* Wd   = (const float*)d_in[1];
    const float* bd   = (const float*)d_in[2];
    const float* Wq   = (const float*)d_in[3];
    const float* bq   = (const float*)d_in[4];
    const float* Wk   = (const float*)d_in[5];
    const float* bk   = (const float*)d_in[6];
    const float* Wv   = (const float*)d_in[7];
    const float* bv   = (const float*)d_in[8];
    const float* gq   = (const float*)d_in[9];
    const float* bqln = (const float*)d_in[10];
    const float* gk   = (const float*)d_in[11];
    const float* bkln = (const float*)d_in[12];
    const float* W1   = (const float*)d_in[13];
    const float* W2   = (const float*)d_in[14];
    const float* Wu   = (const float*)d_in[15];
    const float* bu   = (const float*)d_in[16];
    const float* lr   = (const float*)d_in[17];
    const float* ff   = (const float*)d_in[18];
    float* out = (float*)d_out;

    bf16 *xb, *hb, *qb, *kb, *pb, *rb;
    bf16 *Wdb, *Wqb, *Wkb, *Wvb, *W1b, *W2b, *Wub;
    float *qf, *kf, *v, *u, *loc, *carry, *pref;
    cudaGetSymbolAddress((void**)&xb,  g_xb);
    cudaGetSymbolAddress((void**)&hb,  g_hb);
    cudaGetSymbolAddress((void**)&qb,  g_qb);
    cudaGetSymbolAddress((void**)&kb,  g_kb);
    cudaGetSymbolAddress((void**)&pb,  g_pb);
    cudaGetSymbolAddress((void**)&rb,  g_rb);
    cudaGetSymbolAddress((void**)&qf,  g_qf);
    cudaGetSymbolAddress((void**)&kf,  g_kf);
    cudaGetSymbolAddress((void**)&v,   g_v);
    cudaGetSymbolAddress((void**)&u,   g_u);
    cudaGetSymbolAddress((void**)&loc, g_loc);
    cudaGetSymbolAddress((void**)&carry, g_carry);
    cudaGetSymbolAddress((void**)&pref,  g_pref);
    cudaGetSymbolAddress((void**)&Wdb, g_Wdb);
    cudaGetSymbolAddress((void**)&Wqb, g_Wqb);
    cudaGetSymbolAddress((void**)&Wkb, g_Wkb);
    cudaGetSymbolAddress((void**)&Wvb, g_Wvb);
    cudaGetSymbolAddress((void**)&W1b, g_W1b);
    cudaGetSymbolAddress((void**)&W2b, g_W2b);
    cudaGetSymbolAddress((void**)&Wub, g_Wub);

    // conversions
    cvt_kernel<<<(ROWS * DDIM / 4 + 255) / 256, 256>>>(x,  xb,  ROWS * DDIM / 4);
    cvt_kernel<<<(DDIM * MDIM / 4 + 255) / 256, 256>>>(Wd, Wdb, DDIM * MDIM / 4);
    cvt_kernel<<<(MDIM * MDIM / 4 + 255) / 256, 256>>>(Wq, Wqb, MDIM * MDIM / 4);
    cvt_kernel<<<(MDIM * MDIM / 4 + 255) / 256, 256>>>(Wk, Wkb, MDIM * MDIM / 4);
    cvt_kernel<<<(MDIM * MDIM / 4 + 255) / 256, 256>>>(Wv, Wvb, MDIM * MDIM / 4);
    cvt_kernel<<<(MDIM * MDIM / 4 + 255) / 256, 256>>>(W1, W1b, MDIM * MDIM / 4);
    cvt_kernel<<<(MDIM * MDIM / 4 + 255) / 256, 256>>>(W2, W2b, MDIM * MDIM / 4);
    cvt_kernel<<<(MDIM * DDIM / 4 + 255) / 256, 256>>>(Wu, Wub, MDIM * DDIM / 4);

    dim3 tb(256);
    dim3 gM(MDIM / BN, ROWS / BM);   // (4, 256)
    dim3 gD(DDIM / BN, ROWS / BM);   // (8, 256)

    // h = x@Wd + bd  -> bf16
    mma_gemm<0, true ><<<gM, tb>>>(xb, Wdb, bd, nullptr, nullptr, nullptr, hb, DDIM, MDIM);
    // q-hat / k-hat (fp32 for LN), v (fp32)
    mma_gemm<0, false><<<gM, tb>>>(hb, Wqb, bq, nullptr, nullptr, qf, nullptr, MDIM, MDIM);
    mma_gemm<0, false><<<gM, tb>>>(hb, Wkb, bk, nullptr, nullptr, kf, nullptr, MDIM, MDIM);
    mma_gemm<0, false><<<gM, tb>>>(hb, Wvb, bv, nullptr, nullptr, v,  nullptr, MDIM, MDIM);
    // LayerNorms -> bf16
    ln_kernel<<<ROWS / 8, 256>>>(qf, gq, bqln, qb);
    ln_kernel<<<ROWS / 8, 256>>>(kf, gk, bkln, kb);
    // P = gelu(k@W1) -> bf16
    mma_gemm<1, true ><<<gM, tb>>>(kb, W1b, nullptr, nullptr, nullptr, nullptr, pb, MDIM, MDIM);
    // u = lr*(v - P@W2) -> fp32
    mma_gemm<2, false><<<gM, tb>>>(pb, W2b, nullptr, v, lr, u, nullptr, MDIM, MDIM);
    // scan
    scan1<<<dim3(NCHUNK, BATCH), MDIM>>>(u, loc, carry, ff);
    scan2<<<BATCH, MDIM>>>(carry, pref, ff);
    scan3<<<dim3(NCHUNK, BATCH), MDIM>>>(loc, pref, qb, rb, ff);
    // out = x + ret@Wu + bu
    mma_gemm<3, false><<<gD, tb>>>(rb, Wub, bu, x, nullptr, out, nullptr, MDIM, DDIM);
}